// round 6
// baseline (speedup 1.0000x reference)
#include <cuda_runtime.h>
#include <math.h>

// CellularAutomatonDecoder: B=2048, T=32, D=128, V=256, CDIM=128, 8 evolve steps.
// Fully fused fp32 implementation using packed f32x2 FMA (Blackwell FFMA2).
//
// Kernel 1 (prep, 1 block): a = sigmoid(alpha); const_bias = gelu(mean(c)@Wc1+bc1)@Wc2+bc2 @ W1b + b1
// Kernel 2 (evolve, 512 blocks): each CTA owns 4 batch rows (128 cells rows) in SMEM,
//   runs 8 evolution steps (3 rolled matmuls + gelu + W2 + tanh + mix), LayerNorm, head matmul.

typedef unsigned long long u64;

__device__ float g_const_bias[256];
__device__ float g_alpha_sig;

__device__ __forceinline__ u64 pack2(float lo, float hi){
    u64 r; asm("mov.b64 %0,{%1,%2};" : "=l"(r) : "f"(lo), "f"(hi)); return r;
}
__device__ __forceinline__ float2 unpack2(u64 v){
    float2 f; asm("mov.b64 {%0,%1},%2;" : "=f"(f.x), "=f"(f.y) : "l"(v)); return f;
}
// packed fp32x2 FMA: d = a*b + d (lanewise, round-to-nearest; exact fp32 semantics)
__device__ __forceinline__ void fma2(u64& d, u64 a, u64 b){
    asm("fma.rn.f32x2 %0,%1,%2,%0;" : "+l"(d) : "l"(a), "l"(b));
}
__device__ __forceinline__ float gelu_exact(float x){
    return 0.5f * x * (1.0f + erff(x * 0.70710678118654752440f));
}

// ---------------------------------------------------------------------------
// Prep kernel: tiny, one block of 256 threads.
// ---------------------------------------------------------------------------
__global__ void prep_kernel(const float* __restrict__ c_states,
                            const float* __restrict__ Wc1,
                            const float* __restrict__ bc1,
                            const float* __restrict__ Wc2,
                            const float* __restrict__ bc2,
                            const float* __restrict__ W1,
                            const float* __restrict__ b1,
                            const float* __restrict__ alpha)
{
    __shared__ float cp[128];
    __shared__ float h1[256];
    __shared__ float rb[128];
    const int tid = threadIdx.x;

    if (tid < 128)
        cp[tid] = 0.25f * (c_states[tid] + c_states[128+tid] + c_states[256+tid] + c_states[384+tid]);
    __syncthreads();

    {   // h1 = gelu(c_pooled @ Wc1 + bc1), n = tid (0..255)
        float s = bc1[tid];
        #pragma unroll 4
        for (int d = 0; d < 128; ++d) s += cp[d] * Wc1[d*256 + tid];
        h1[tid] = gelu_exact(s);
    }
    __syncthreads();

    if (tid < 128) {  // rule_bias = h1 @ Wc2 + bc2
        float s = bc2[tid];
        #pragma unroll 4
        for (int n = 0; n < 256; ++n) s += h1[n] * Wc2[n*128 + tid];
        rb[tid] = s;
    }
    __syncthreads();

    {   // const_bias = rule_bias @ W1b + b1   (W1b = W1 rows [384:512))
        float s = b1[tid];
        #pragma unroll 4
        for (int d = 0; d < 128; ++d) s += rb[d] * W1[(384 + d)*256 + tid];
        g_const_bias[tid] = s;
    }
    if (tid == 0) g_alpha_sig = 1.0f / (1.0f + expf(-alpha[0]));
}

// ---------------------------------------------------------------------------
// Main fused kernel. 512 blocks x 256 threads. 96KB dynamic SMEM:
//   cells[128][128]  (fp32)   64KB
//   Hs   [128][64]   (fp32)   32KB  (gelu(pre) chunk buffer)
// Thread layout: tx = tid&15 (N dim), ty = tid>>4 (M dim); each thread owns
// rows m = ty + 16*i (i<8).
// ---------------------------------------------------------------------------
__global__ void __launch_bounds__(256)
evolve_kernel(const int*   __restrict__ tokens,
              const float* __restrict__ embed,
              const float* __restrict__ pos_embed,
              const float* __restrict__ W1,
              const float* __restrict__ W2,
              const float* __restrict__ b2,
              const float* __restrict__ ln_g,
              const float* __restrict__ ln_b,
              const float* __restrict__ head_w,
              float*       __restrict__ out)
{
    extern __shared__ float smem[];
    float* cells = smem;             // 128*128
    float* Hs    = smem + 128*128;   // 128*64

    const int tid = threadIdx.x;
    const int tx  = tid & 15;
    const int ty  = tid >> 4;
    const int rowbase = blockIdx.x * 128;    // flattened (b*32 + t) base

    // ---- load cells = embed[token] + pos_embed ----
    for (int idx = tid; idx < 128*32; idx += 256) {
        const int m = idx >> 5;
        const int q = (idx & 31) << 2;
        const int g = rowbase + m;
        const int tok = __ldg(tokens + g);
        const float4 e = *reinterpret_cast<const float4*>(embed + tok*128 + q);
        const float4 p = *reinterpret_cast<const float4*>(pos_embed + (g & 31)*128 + q);
        float4 c; c.x = e.x + p.x; c.y = e.y + p.y; c.z = e.z + p.z; c.w = e.w + p.w;
        *reinterpret_cast<float4*>(cells + m*128 + q) = c;
    }
    const float a  = g_alpha_sig;
    const float om = 1.0f - a;
    __syncthreads();

    // ================= 8 evolution steps =================
    for (int step = 0; step < 8; ++step) {
        // matmul2 accumulators: new_cells pre-activation, 8 rows x 8 cols = 32 packed pairs
        u64 acc2[8][4];
        #pragma unroll
        for (int i = 0; i < 8; ++i) {
            acc2[i][0] = 0ULL; acc2[i][1] = 0ULL; acc2[i][2] = 0ULL; acc2[i][3] = 0ULL;
        }

        for (int c2 = 0; c2 < 4; ++c2) {
            const int n0 = c2 * 64;

            // ---- matmul1: pre[:, n0:n0+64] = X @ W1[c|l|r] + const_bias ----
            u64 acc1[8][2];
            {
                const float* cbp = g_const_bias + n0 + tx*4;
                const u64 p0 = pack2(cbp[0], cbp[1]);
                const u64 p1 = pack2(cbp[2], cbp[3]);
                #pragma unroll
                for (int i = 0; i < 8; ++i) { acc1[i][0] = p0; acc1[i][1] = p1; }
            }
            #pragma unroll
            for (int j = 0; j < 3; ++j) {
                const int dj = (j == 0) ? 0 : ((j == 1) ? 31 : 1);  // self, left (t-1), right (t+1)
                const float* Wj = W1 + j*(128*256) + n0 + tx*4;
                int roff[8];
                #pragma unroll
                for (int i = 0; i < 8; ++i) {
                    const int m = ty + 16*i;
                    roff[i] = ((m & 96) | ((m + dj) & 31)) << 7;   // circular roll within 32-row batch
                }
                for (int k = 0; k < 128; k += 4) {
                    const ulonglong2 w0  = *reinterpret_cast<const ulonglong2*>(Wj + (k+0)*256);
                    const ulonglong2 w1  = *reinterpret_cast<const ulonglong2*>(Wj + (k+1)*256);
                    const ulonglong2 w2v = *reinterpret_cast<const ulonglong2*>(Wj + (k+2)*256);
                    const ulonglong2 w3  = *reinterpret_cast<const ulonglong2*>(Wj + (k+3)*256);
                    #pragma unroll
                    for (int i = 0; i < 8; ++i) {
                        const float4 av = *reinterpret_cast<const float4*>(cells + roff[i] + k);
                        const u64 ax = pack2(av.x, av.x), ay = pack2(av.y, av.y);
                        const u64 az = pack2(av.z, av.z), aw = pack2(av.w, av.w);
                        fma2(acc1[i][0], ax, w0.x);  fma2(acc1[i][1], ax, w0.y);
                        fma2(acc1[i][0], ay, w1.x);  fma2(acc1[i][1], ay, w1.y);
                        fma2(acc1[i][0], az, w2v.x); fma2(acc1[i][1], az, w2v.y);
                        fma2(acc1[i][0], aw, w3.x);  fma2(acc1[i][1], aw, w3.y);
                    }
                }
            }

            __syncthreads();   // prior chunk's matmul2 done reading Hs
            #pragma unroll
            for (int i = 0; i < 8; ++i) {
                const int m = ty + 16*i;
                const float2 f0 = unpack2(acc1[i][0]);
                const float2 f1 = unpack2(acc1[i][1]);
                float4 h;
                h.x = gelu_exact(f0.x); h.y = gelu_exact(f0.y);
                h.z = gelu_exact(f1.x); h.w = gelu_exact(f1.y);
                *reinterpret_cast<float4*>(Hs + m*64 + tx*4) = h;
            }
            __syncthreads();   // Hs chunk ready

            // ---- matmul2 partial: acc2 += Hs(128x64) @ W2[n0:n0+64, :] ----
            const float* W2p = W2 + n0*128 + tx*8;
            for (int k = 0; k < 64; k += 2) {
                const ulonglong2 c0 = *reinterpret_cast<const ulonglong2*>(W2p + (k+0)*128);
                const ulonglong2 c1 = *reinterpret_cast<const ulonglong2*>(W2p + (k+0)*128 + 4);
                const ulonglong2 d0 = *reinterpret_cast<const ulonglong2*>(W2p + (k+1)*128);
                const ulonglong2 d1 = *reinterpret_cast<const ulonglong2*>(W2p + (k+1)*128 + 4);
                #pragma unroll
                for (int i = 0; i < 8; ++i) {
                    const int m = ty + 16*i;
                    const float2 hv = *reinterpret_cast<const float2*>(Hs + m*64 + k);
                    const u64 h0 = pack2(hv.x, hv.x), h1 = pack2(hv.y, hv.y);
                    fma2(acc2[i][0], h0, c0.x); fma2(acc2[i][1], h0, c0.y);
                    fma2(acc2[i][2], h0, c1.x); fma2(acc2[i][3], h0, c1.y);
                    fma2(acc2[i][0], h1, d0.x); fma2(acc2[i][1], h1, d0.y);
                    fma2(acc2[i][2], h1, d1.x); fma2(acc2[i][3], h1, d1.y);
                }
            }
        } // n-chunks

        // ---- cells = a*cells + (1-a)*tanh(acc2 + b2) ----
        {
            const float* b2p = b2 + tx*8;
            float bb[8];
            #pragma unroll
            for (int q = 0; q < 8; ++q) bb[q] = b2p[q];
            #pragma unroll
            for (int i = 0; i < 8; ++i) {
                const int m = ty + 16*i;
                float* crow = cells + m*128 + tx*8;
                float4 o0 = *reinterpret_cast<const float4*>(crow);
                float4 o1 = *reinterpret_cast<const float4*>(crow + 4);
                const float2 v0 = unpack2(acc2[i][0]);
                const float2 v1 = unpack2(acc2[i][1]);
                const float2 v2 = unpack2(acc2[i][2]);
                const float2 v3 = unpack2(acc2[i][3]);
                o0.x = a*o0.x + om*tanhf(v0.x + bb[0]);
                o0.y = a*o0.y + om*tanhf(v0.y + bb[1]);
                o0.z = a*o0.z + om*tanhf(v1.x + bb[2]);
                o0.w = a*o0.w + om*tanhf(v1.y + bb[3]);
                o1.x = a*o1.x + om*tanhf(v2.x + bb[4]);
                o1.y = a*o1.y + om*tanhf(v2.y + bb[5]);
                o1.z = a*o1.z + om*tanhf(v3.x + bb[6]);
                o1.w = a*o1.w + om*tanhf(v3.y + bb[7]);
                *reinterpret_cast<float4*>(crow)     = o0;
                *reinterpret_cast<float4*>(crow + 4) = o1;
            }
        }
        __syncthreads();
    } // steps

    // ================= LayerNorm (per row over D=128) =================
    if (tid < 128) {
        float* crow = cells + tid*128;
        float s = 0.f, ss = 0.f;
        #pragma unroll 8
        for (int q = 0; q < 128; q += 4) {
            const float4 v = *reinterpret_cast<const float4*>(crow + q);
            s  += v.x + v.y + v.z + v.w;
            ss += v.x*v.x + v.y*v.y + v.z*v.z + v.w*v.w;
        }
        const float mu  = s * 0.0078125f;
        const float var = ss * 0.0078125f - mu*mu;
        const float inv = rsqrtf(var + 1e-5f);
        #pragma unroll 8
        for (int q = 0; q < 128; q += 4) {
            float4 v = *reinterpret_cast<const float4*>(crow + q);
            const float4 g4 = *reinterpret_cast<const float4*>(ln_g + q);
            const float4 b4 = *reinterpret_cast<const float4*>(ln_b + q);
            v.x = (v.x - mu)*inv*g4.x + b4.x;
            v.y = (v.y - mu)*inv*g4.y + b4.y;
            v.z = (v.z - mu)*inv*g4.z + b4.z;
            v.w = (v.w - mu)*inv*g4.w + b4.w;
            *reinterpret_cast<float4*>(crow + q) = v;
        }
    }
    __syncthreads();

    // ================= head: out = cells @ head_w (128x128 @ 128x256) =================
    float* outp = out + (size_t)rowbase * 256;
    for (int c2 = 0; c2 < 4; ++c2) {
        const int n0 = c2 * 64;
        u64 acc[8][2];
        #pragma unroll
        for (int i = 0; i < 8; ++i) { acc[i][0] = 0ULL; acc[i][1] = 0ULL; }
        const float* Hw = head_w + n0 + tx*4;
        for (int k = 0; k < 128; k += 4) {
            const ulonglong2 w0  = *reinterpret_cast<const ulonglong2*>(Hw + (k+0)*256);
            const ulonglong2 w1  = *reinterpret_cast<const ulonglong2*>(Hw + (k+1)*256);
            const ulonglong2 w2v = *reinterpret_cast<const ulonglong2*>(Hw + (k+2)*256);
            const ulonglong2 w3  = *reinterpret_cast<const ulonglong2*>(Hw + (k+3)*256);
            #pragma unroll
            for (int i = 0; i < 8; ++i) {
                const float4 av = *reinterpret_cast<const float4*>(cells + ((ty + 16*i) << 7) + k);
                const u64 ax = pack2(av.x, av.x), ay = pack2(av.y, av.y);
                const u64 az = pack2(av.z, av.z), aw = pack2(av.w, av.w);
                fma2(acc[i][0], ax, w0.x);  fma2(acc[i][1], ax, w0.y);
                fma2(acc[i][0], ay, w1.x);  fma2(acc[i][1], ay, w1.y);
                fma2(acc[i][0], az, w2v.x); fma2(acc[i][1], az, w2v.y);
                fma2(acc[i][0], aw, w3.x);  fma2(acc[i][1], aw, w3.y);
            }
        }
        #pragma unroll
        for (int i = 0; i < 8; ++i) {
            const int m = ty + 16*i;
            const float2 f0 = unpack2(acc[i][0]);
            const float2 f1 = unpack2(acc[i][1]);
            float4 o; o.x = f0.x; o.y = f0.y; o.z = f1.x; o.w = f1.y;
            *reinterpret_cast<float4*>(outp + m*256 + n0 + tx*4) = o;
        }
    }
}

// ---------------------------------------------------------------------------
extern "C" void kernel_launch(void* const* d_in, const int* in_sizes, int n_in,
                              void* d_out, int out_size)
{
    const int*   tokens    = (const int*)  d_in[0];
    const float* c_states  = (const float*)d_in[1];
    const float* embed     = (const float*)d_in[2];
    const float* pos_embed = (const float*)d_in[3];
    const float* W1        = (const float*)d_in[4];
    const float* b1        = (const float*)d_in[5];
    const float* W2        = (const float*)d_in[6];
    const float* b2        = (const float*)d_in[7];
    const float* Wc1       = (const float*)d_in[8];
    const float* bc1       = (const float*)d_in[9];
    const float* Wc2       = (const float*)d_in[10];
    const float* bc2       = (const float*)d_in[11];
    const float* alpha     = (const float*)d_in[12];
    const float* ln_g      = (const float*)d_in[13];
    const float* ln_b      = (const float*)d_in[14];
    const float* head_w    = (const float*)d_in[15];
    float* out = (float*)d_out;

    // 96KB dynamic SMEM (cells 64KB + hidden-chunk 32KB); idempotent, capture-safe.
    cudaFuncSetAttribute(evolve_kernel, cudaFuncAttributeMaxDynamicSharedMemorySize, 98304);

    prep_kernel<<<1, 256>>>(c_states, Wc1, bc1, Wc2, bc2, W1, b1, alpha);
    evolve_kernel<<<512, 256, 98304>>>(tokens, embed, pos_embed, W1, W2, b2,
                                       ln_g, ln_b, head_w, out);
}

// round 7
// speedup vs baseline: 1.0753x; 1.0753x over previous
#include <cuda_runtime.h>
#include <math.h>

// CellularAutomatonDecoder: B=2048, T=32, D=128, V=256, 8 evolve steps.
// fp32 via packed f32x2 FMA (FFMA2). Round 6: k-pair-packed weights (no MOV
// duplication in hot loops) + 64-row CTAs at 2 CTAs/SM.

typedef unsigned long long u64;

__device__ float g_const_bias[256];
__device__ float g_alpha_sig;
__device__ u64   g_W1p[3 * 64 * 256];   // W1 rolled slices, k-pair packed
__device__ u64   g_Hp [64 * 256];       // head_w, k-pair packed

__device__ __forceinline__ u64 pack2(float lo, float hi){
    u64 r; asm("mov.b64 %0,{%1,%2};" : "=l"(r) : "f"(lo), "f"(hi)); return r;
}
__device__ __forceinline__ float2 unpack2(u64 v){
    float2 f; asm("mov.b64 {%0,%1},%2;" : "=f"(f.x), "=f"(f.y) : "l"(v)); return f;
}
// packed fp32x2 FMA: d = a*b + d (lanewise, exact fp32 semantics)
__device__ __forceinline__ void fma2(u64& d, u64 a, u64 b){
    asm("fma.rn.f32x2 %0,%1,%2,%0;" : "+l"(d) : "l"(a), "l"(b));
}
__device__ __forceinline__ float gelu_exact(float x){
    return 0.5f * x * (1.0f + erff(x * 0.70710678118654752440f));
}

// ---------------------------------------------------------------------------
// Prep: a = sigmoid(alpha); const_bias = (gelu(mean(c)@Wc1+bc1)@Wc2+bc2)@W1b + b1
// ---------------------------------------------------------------------------
__global__ void prep_kernel(const float* __restrict__ c_states,
                            const float* __restrict__ Wc1,
                            const float* __restrict__ bc1,
                            const float* __restrict__ Wc2,
                            const float* __restrict__ bc2,
                            const float* __restrict__ W1,
                            const float* __restrict__ b1,
                            const float* __restrict__ alpha)
{
    __shared__ float cp[128];
    __shared__ float h1[256];
    __shared__ float rb[128];
    const int tid = threadIdx.x;

    if (tid < 128)
        cp[tid] = 0.25f * (c_states[tid] + c_states[128+tid] + c_states[256+tid] + c_states[384+tid]);
    __syncthreads();

    {
        float s = bc1[tid];
        #pragma unroll 4
        for (int d = 0; d < 128; ++d) s += cp[d] * Wc1[d*256 + tid];
        h1[tid] = gelu_exact(s);
    }
    __syncthreads();

    if (tid < 128) {
        float s = bc2[tid];
        #pragma unroll 4
        for (int n = 0; n < 256; ++n) s += h1[n] * Wc2[n*128 + tid];
        rb[tid] = s;
    }
    __syncthreads();

    {
        float s = b1[tid];
        #pragma unroll 4
        for (int d = 0; d < 128; ++d) s += rb[d] * W1[(384 + d)*256 + tid];
        g_const_bias[tid] = s;
    }
    if (tid == 0) g_alpha_sig = 1.0f / (1.0f + expf(-alpha[0]));
}

// ---------------------------------------------------------------------------
// Pack: W1p[j][kp][n] = {W1[j*128+2kp][n], W1[j*128+2kp+1][n]}, same for head.
// 16384 threads total (64 blocks x 256).
// ---------------------------------------------------------------------------
__global__ void pack_kernel(const float* __restrict__ W1,
                            const float* __restrict__ head_w)
{
    const int idx = blockIdx.x * 256 + threadIdx.x;   // 0..16383 = kp*256 + n
    const int kp = idx >> 8;
    const int n  = idx & 255;
    #pragma unroll
    for (int j = 0; j < 3; ++j) {
        const float* base = W1 + (j*128 + 2*kp)*256 + n;
        g_W1p[j*16384 + idx] = pack2(base[0], base[256]);
    }
    const float* hb = head_w + 2*kp*256 + n;
    g_Hp[idx] = pack2(hb[0], hb[256]);
}

// ---------------------------------------------------------------------------
// Main fused kernel. 1024 blocks x 256 threads, 2 CTAs/SM, 48KB SMEM:
//   cells[64][128] fp32 (32KB) + Hs[64][64] fp32 (16KB)
// tx = tid&15 (N dim), ty = tid>>4; thread owns rows m = ty + 16*i, i<4.
// matmul1/head: k-pair packed (act u64 straight from LDS.128 halves, no MOVs).
// Accumulator lanes = (even-k partial [+const_bias], odd-k partial); reduced
// once per chunk before gelu.
// ---------------------------------------------------------------------------
__global__ void __launch_bounds__(256, 2)
evolve_kernel(const int*   __restrict__ tokens,
              const float* __restrict__ embed,
              const float* __restrict__ pos_embed,
              const float* __restrict__ W2,
              const float* __restrict__ b2,
              const float* __restrict__ ln_g,
              const float* __restrict__ ln_b,
              float*       __restrict__ out)
{
    extern __shared__ float smem[];
    float* cells = smem;            // 64*128
    float* Hs    = smem + 64*128;   // 64*64

    const int tid = threadIdx.x;
    const int tx  = tid & 15;
    const int ty  = tid >> 4;
    const int rowbase = blockIdx.x * 64;    // flattened (b*32 + t) base

    // ---- cells = embed[token] + pos_embed ----
    for (int idx = tid; idx < 64*32; idx += 256) {
        const int m = idx >> 5;
        const int q = (idx & 31) << 2;
        const int g = rowbase + m;
        const int tok = __ldg(tokens + g);
        const float4 e = *reinterpret_cast<const float4*>(embed + tok*128 + q);
        const float4 p = *reinterpret_cast<const float4*>(pos_embed + (g & 31)*128 + q);
        float4 c; c.x = e.x + p.x; c.y = e.y + p.y; c.z = e.z + p.z; c.w = e.w + p.w;
        *reinterpret_cast<float4*>(cells + m*128 + q) = c;
    }
    const float a  = g_alpha_sig;
    const float om = 1.0f - a;
    __syncthreads();

    // ================= 8 evolution steps =================
    #pragma unroll 1
    for (int step = 0; step < 8; ++step) {
        u64 acc2[4][4];   // matmul2 accum: 4 rows x 8 cols (adjacent col pairs)
        #pragma unroll
        for (int i = 0; i < 4; ++i) {
            acc2[i][0] = 0ULL; acc2[i][1] = 0ULL; acc2[i][2] = 0ULL; acc2[i][3] = 0ULL;
        }

        #pragma unroll 1
        for (int c2 = 0; c2 < 4; ++c2) {
            const int n0 = c2 * 64;

            // ---- matmul1 (k-pair packed): pre[:, n0:n0+64] ----
            u64 acc1[4][4];   // lanes: (even-k sum + const_bias, odd-k sum)
            {
                const float4 cb = *reinterpret_cast<const float4*>(g_const_bias + n0 + tx*4);
                #pragma unroll
                for (int i = 0; i < 4; ++i) {
                    acc1[i][0] = pack2(cb.x, 0.0f); acc1[i][1] = pack2(cb.y, 0.0f);
                    acc1[i][2] = pack2(cb.z, 0.0f); acc1[i][3] = pack2(cb.w, 0.0f);
                }
            }
            #pragma unroll
            for (int j = 0; j < 3; ++j) {
                const int dj = (j == 0) ? 0 : ((j == 1) ? 31 : 1);  // self, left, right
                int roff[4];
                #pragma unroll
                for (int i = 0; i < 4; ++i) {
                    const int m = ty + 16*i;
                    roff[i] = ((m & 32) | ((m + dj) & 31)) << 7;  // roll within 32-row group
                }
                const u64* Wj = g_W1p + j*16384 + n0 + tx*4;
                #pragma unroll 4
                for (int k0 = 0; k0 < 128; k0 += 4) {
                    const u64* wp = Wj + (k0 >> 1) * 256;
                    const ulonglong2 wA = *reinterpret_cast<const ulonglong2*>(wp);
                    const ulonglong2 wB = *reinterpret_cast<const ulonglong2*>(wp + 2);
                    const ulonglong2 wC = *reinterpret_cast<const ulonglong2*>(wp + 256);
                    const ulonglong2 wD = *reinterpret_cast<const ulonglong2*>(wp + 258);
                    #pragma unroll
                    for (int i = 0; i < 4; ++i) {
                        const ulonglong2 av = *reinterpret_cast<const ulonglong2*>(cells + roff[i] + k0);
                        fma2(acc1[i][0], av.x, wA.x); fma2(acc1[i][1], av.x, wA.y);
                        fma2(acc1[i][2], av.x, wB.x); fma2(acc1[i][3], av.x, wB.y);
                        fma2(acc1[i][0], av.y, wC.x); fma2(acc1[i][1], av.y, wC.y);
                        fma2(acc1[i][2], av.y, wD.x); fma2(acc1[i][3], av.y, wD.y);
                    }
                }
            }

            __syncthreads();   // prior chunk's matmul2 finished reading Hs
            #pragma unroll
            for (int i = 0; i < 4; ++i) {
                const int m = ty + 16*i;
                const float2 f0 = unpack2(acc1[i][0]);
                const float2 f1 = unpack2(acc1[i][1]);
                const float2 f2 = unpack2(acc1[i][2]);
                const float2 f3 = unpack2(acc1[i][3]);
                float4 h;
                h.x = gelu_exact(f0.x + f0.y);
                h.y = gelu_exact(f1.x + f1.y);
                h.z = gelu_exact(f2.x + f2.y);
                h.w = gelu_exact(f3.x + f3.y);
                *reinterpret_cast<float4*>(Hs + m*64 + tx*4) = h;
            }
            __syncthreads();   // Hs chunk ready

            // ---- matmul2 partial: acc2 += Hs(64x64) @ W2[n0:n0+64, :] ----
            const float* W2p = W2 + n0*128 + tx*8;
            #pragma unroll 4
            for (int k = 0; k < 64; k += 2) {
                const ulonglong2 c0 = *reinterpret_cast<const ulonglong2*>(W2p + (k+0)*128);
                const ulonglong2 c1 = *reinterpret_cast<const ulonglong2*>(W2p + (k+0)*128 + 4);
                const ulonglong2 d0 = *reinterpret_cast<const ulonglong2*>(W2p + (k+1)*128);
                const ulonglong2 d1 = *reinterpret_cast<const ulonglong2*>(W2p + (k+1)*128 + 4);
                #pragma unroll
                for (int i = 0; i < 4; ++i) {
                    const int m = ty + 16*i;
                    const float2 hv = *reinterpret_cast<const float2*>(Hs + m*64 + k);
                    const u64 h0 = pack2(hv.x, hv.x), h1 = pack2(hv.y, hv.y);
                    fma2(acc2[i][0], h0, c0.x); fma2(acc2[i][1], h0, c0.y);
                    fma2(acc2[i][2], h0, c1.x); fma2(acc2[i][3], h0, c1.y);
                    fma2(acc2[i][0], h1, d0.x); fma2(acc2[i][1], h1, d0.y);
                    fma2(acc2[i][2], h1, d1.x); fma2(acc2[i][3], h1, d1.y);
                }
            }
        } // n-chunks

        // ---- cells = a*cells + (1-a)*tanh(acc2 + b2) ----
        {
            const float* b2p = b2 + tx*8;
            float bb[8];
            #pragma unroll
            for (int q = 0; q < 8; ++q) bb[q] = b2p[q];
            #pragma unroll
            for (int i = 0; i < 4; ++i) {
                const int m = ty + 16*i;
                float* crow = cells + m*128 + tx*8;
                float4 o0 = *reinterpret_cast<const float4*>(crow);
                float4 o1 = *reinterpret_cast<const float4*>(crow + 4);
                const float2 v0 = unpack2(acc2[i][0]);
                const float2 v1 = unpack2(acc2[i][1]);
                const float2 v2 = unpack2(acc2[i][2]);
                const float2 v3 = unpack2(acc2[i][3]);
                o0.x = a*o0.x + om*tanhf(v0.x + bb[0]);
                o0.y = a*o0.y + om*tanhf(v0.y + bb[1]);
                o0.z = a*o0.z + om*tanhf(v1.x + bb[2]);
                o0.w = a*o0.w + om*tanhf(v1.y + bb[3]);
                o1.x = a*o1.x + om*tanhf(v2.x + bb[4]);
                o1.y = a*o1.y + om*tanhf(v2.y + bb[5]);
                o1.z = a*o1.z + om*tanhf(v3.x + bb[6]);
                o1.w = a*o1.w + om*tanhf(v3.y + bb[7]);
                *reinterpret_cast<float4*>(crow)     = o0;
                *reinterpret_cast<float4*>(crow + 4) = o1;
            }
        }
        __syncthreads();
    } // steps

    // ================= LayerNorm (per row over D=128) =================
    if (tid < 64) {
        float* crow = cells + tid*128;
        float s = 0.f, ss = 0.f;
        #pragma unroll 8
        for (int q = 0; q < 128; q += 4) {
            const float4 v = *reinterpret_cast<const float4*>(crow + q);
            s  += v.x + v.y + v.z + v.w;
            ss += v.x*v.x + v.y*v.y + v.z*v.z + v.w*v.w;
        }
        const float mu  = s * 0.0078125f;
        const float var = ss * 0.0078125f - mu*mu;
        const float inv = rsqrtf(var + 1e-5f);
        #pragma unroll 8
        for (int q = 0; q < 128; q += 4) {
            float4 v = *reinterpret_cast<const float4*>(crow + q);
            const float4 g4 = *reinterpret_cast<const float4*>(ln_g + q);
            const float4 b4 = *reinterpret_cast<const float4*>(ln_b + q);
            v.x = (v.x - mu)*inv*g4.x + b4.x;
            v.y = (v.y - mu)*inv*g4.y + b4.y;
            v.z = (v.z - mu)*inv*g4.z + b4.z;
            v.w = (v.w - mu)*inv*g4.w + b4.w;
            *reinterpret_cast<float4*>(crow + q) = v;
        }
    }
    __syncthreads();

    // ================= head (k-pair packed): out = cells @ head_w =================
    float* outp = out + (size_t)rowbase * 256;
    #pragma unroll 1
    for (int c2 = 0; c2 < 4; ++c2) {
        const int n0 = c2 * 64;
        u64 acc[4][4];
        #pragma unroll
        for (int i = 0; i < 4; ++i) {
            acc[i][0] = 0ULL; acc[i][1] = 0ULL; acc[i][2] = 0ULL; acc[i][3] = 0ULL;
        }
        const u64* Hw = g_Hp + n0 + tx*4;
        #pragma unroll 4
        for (int k0 = 0; k0 < 128; k0 += 4) {
            const u64* wp = Hw + (k0 >> 1) * 256;
            const ulonglong2 wA = *reinterpret_cast<const ulonglong2*>(wp);
            const ulonglong2 wB = *reinterpret_cast<const ulonglong2*>(wp + 2);
            const ulonglong2 wC = *reinterpret_cast<const ulonglong2*>(wp + 256);
            const ulonglong2 wD = *reinterpret_cast<const ulonglong2*>(wp + 258);
            #pragma unroll
            for (int i = 0; i < 4; ++i) {
                const ulonglong2 av = *reinterpret_cast<const ulonglong2*>(cells + ((ty + 16*i) << 7) + k0);
                fma2(acc[i][0], av.x, wA.x); fma2(acc[i][1], av.x, wA.y);
                fma2(acc[i][2], av.x, wB.x); fma2(acc[i][3], av.x, wB.y);
                fma2(acc[i][0], av.y, wC.x); fma2(acc[i][1], av.y, wC.y);
                fma2(acc[i][2], av.y, wD.x); fma2(acc[i][3], av.y, wD.y);
            }
        }
        #pragma unroll
        for (int i = 0; i < 4; ++i) {
            const int m = ty + 16*i;
            const float2 f0 = unpack2(acc[i][0]);
            const float2 f1 = unpack2(acc[i][1]);
            const float2 f2 = unpack2(acc[i][2]);
            const float2 f3 = unpack2(acc[i][3]);
            float4 o;
            o.x = f0.x + f0.y; o.y = f1.x + f1.y;
            o.z = f2.x + f2.y; o.w = f3.x + f3.y;
            *reinterpret_cast<float4*>(outp + m*256 + n0 + tx*4) = o;
        }
    }
}

// ---------------------------------------------------------------------------
extern "C" void kernel_launch(void* const* d_in, const int* in_sizes, int n_in,
                              void* d_out, int out_size)
{
    const int*   tokens    = (const int*)  d_in[0];
    const float* c_states  = (const float*)d_in[1];
    const float* embed     = (const float*)d_in[2];
    const float* pos_embed = (const float*)d_in[3];
    const float* W1        = (const float*)d_in[4];
    const float* b1        = (const float*)d_in[5];
    const float* W2        = (const float*)d_in[6];
    const float* b2        = (const float*)d_in[7];
    const float* Wc1       = (const float*)d_in[8];
    const float* bc1       = (const float*)d_in[9];
    const float* Wc2       = (const float*)d_in[10];
    const float* bc2       = (const float*)d_in[11];
    const float* alpha     = (const float*)d_in[12];
    const float* ln_g      = (const float*)d_in[13];
    const float* ln_b      = (const float*)d_in[14];
    const float* head_w    = (const float*)d_in[15];
    float* out = (float*)d_out;

    cudaFuncSetAttribute(evolve_kernel, cudaFuncAttributeMaxDynamicSharedMemorySize, 49152);

    prep_kernel<<<1, 256>>>(c_states, Wc1, bc1, Wc2, bc2, W1, b1, alpha);
    pack_kernel<<<64, 256>>>(W1, head_w);
    evolve_kernel<<<1024, 256, 49152>>>(tokens, embed, pos_embed, W2, b2,
                                        ln_g, ln_b, out);
}

// round 8
// speedup vs baseline: 1.0756x; 1.0002x over previous
#include <cuda_runtime.h>
#include <math.h>

// CellularAutomatonDecoder: B=2048, T=32, D=128, V=256, 8 evolve steps.
// fp32 via packed f32x2 FMA (FFMA2). Round 6: k-pair-packed weights (no MOV
// duplication in hot loops) + 64-row CTAs at 2 CTAs/SM.

typedef unsigned long long u64;

__device__ float g_const_bias[256];
__device__ float g_alpha_sig;
__device__ u64   g_W1p[3 * 64 * 256];   // W1 rolled slices, k-pair packed
__device__ u64   g_Hp [64 * 256];       // head_w, k-pair packed

__device__ __forceinline__ u64 pack2(float lo, float hi){
    u64 r; asm("mov.b64 %0,{%1,%2};" : "=l"(r) : "f"(lo), "f"(hi)); return r;
}
__device__ __forceinline__ float2 unpack2(u64 v){
    float2 f; asm("mov.b64 {%0,%1},%2;" : "=f"(f.x), "=f"(f.y) : "l"(v)); return f;
}
// packed fp32x2 FMA: d = a*b + d (lanewise, exact fp32 semantics)
__device__ __forceinline__ void fma2(u64& d, u64 a, u64 b){
    asm("fma.rn.f32x2 %0,%1,%2,%0;" : "+l"(d) : "l"(a), "l"(b));
}
__device__ __forceinline__ float gelu_exact(float x){
    return 0.5f * x * (1.0f + erff(x * 0.70710678118654752440f));
}

// ---------------------------------------------------------------------------
// Prep: a = sigmoid(alpha); const_bias = (gelu(mean(c)@Wc1+bc1)@Wc2+bc2)@W1b + b1
// ---------------------------------------------------------------------------
__global__ void prep_kernel(const float* __restrict__ c_states,
                            const float* __restrict__ Wc1,
                            const float* __restrict__ bc1,
                            const float* __restrict__ Wc2,
                            const float* __restrict__ bc2,
                            const float* __restrict__ W1,
                            const float* __restrict__ b1,
                            const float* __restrict__ alpha)
{
    __shared__ float cp[128];
    __shared__ float h1[256];
    __shared__ float rb[128];
    const int tid = threadIdx.x;

    if (tid < 128)
        cp[tid] = 0.25f * (c_states[tid] + c_states[128+tid] + c_states[256+tid] + c_states[384+tid]);
    __syncthreads();

    {
        float s = bc1[tid];
        #pragma unroll 4
        for (int d = 0; d < 128; ++d) s += cp[d] * Wc1[d*256 + tid];
        h1[tid] = gelu_exact(s);
    }
    __syncthreads();

    if (tid < 128) {
        float s = bc2[tid];
        #pragma unroll 4
        for (int n = 0; n < 256; ++n) s += h1[n] * Wc2[n*128 + tid];
        rb[tid] = s;
    }
    __syncthreads();

    {
        float s = b1[tid];
        #pragma unroll 4
        for (int d = 0; d < 128; ++d) s += rb[d] * W1[(384 + d)*256 + tid];
        g_const_bias[tid] = s;
    }
    if (tid == 0) g_alpha_sig = 1.0f / (1.0f + expf(-alpha[0]));
}

// ---------------------------------------------------------------------------
// Pack: W1p[j][kp][n] = {W1[j*128+2kp][n], W1[j*128+2kp+1][n]}, same for head.
// 16384 threads total (64 blocks x 256).
// ---------------------------------------------------------------------------
__global__ void pack_kernel(const float* __restrict__ W1,
                            const float* __restrict__ head_w)
{
    const int idx = blockIdx.x * 256 + threadIdx.x;   // 0..16383 = kp*256 + n
    const int kp = idx >> 8;
    const int n  = idx & 255;
    #pragma unroll
    for (int j = 0; j < 3; ++j) {
        const float* base = W1 + (j*128 + 2*kp)*256 + n;
        g_W1p[j*16384 + idx] = pack2(base[0], base[256]);
    }
    const float* hb = head_w + 2*kp*256 + n;
    g_Hp[idx] = pack2(hb[0], hb[256]);
}

// ---------------------------------------------------------------------------
// Main fused kernel. 1024 blocks x 256 threads, 2 CTAs/SM, 48KB SMEM:
//   cells[64][128] fp32 (32KB) + Hs[64][64] fp32 (16KB)
// tx = tid&15 (N dim), ty = tid>>4; thread owns rows m = ty + 16*i, i<4.
// matmul1/head: k-pair packed (act u64 straight from LDS.128 halves, no MOVs).
// Accumulator lanes = (even-k partial [+const_bias], odd-k partial); reduced
// once per chunk before gelu.
// ---------------------------------------------------------------------------
__global__ void __launch_bounds__(256, 2)
evolve_kernel(const int*   __restrict__ tokens,
              const float* __restrict__ embed,
              const float* __restrict__ pos_embed,
              const float* __restrict__ W2,
              const float* __restrict__ b2,
              const float* __restrict__ ln_g,
              const float* __restrict__ ln_b,
              float*       __restrict__ out)
{
    extern __shared__ float smem[];
    float* cells = smem;            // 64*128
    float* Hs    = smem + 64*128;   // 64*64

    const int tid = threadIdx.x;
    const int tx  = tid & 15;
    const int ty  = tid >> 4;
    const int rowbase = blockIdx.x * 64;    // flattened (b*32 + t) base

    // ---- cells = embed[token] + pos_embed ----
    for (int idx = tid; idx < 64*32; idx += 256) {
        const int m = idx >> 5;
        const int q = (idx & 31) << 2;
        const int g = rowbase + m;
        const int tok = __ldg(tokens + g);
        const float4 e = *reinterpret_cast<const float4*>(embed + tok*128 + q);
        const float4 p = *reinterpret_cast<const float4*>(pos_embed + (g & 31)*128 + q);
        float4 c; c.x = e.x + p.x; c.y = e.y + p.y; c.z = e.z + p.z; c.w = e.w + p.w;
        *reinterpret_cast<float4*>(cells + m*128 + q) = c;
    }
    const float a  = g_alpha_sig;
    const float om = 1.0f - a;
    __syncthreads();

    // ================= 8 evolution steps =================
    #pragma unroll 1
    for (int step = 0; step < 8; ++step) {
        u64 acc2[4][4];   // matmul2 accum: 4 rows x 8 cols (adjacent col pairs)
        #pragma unroll
        for (int i = 0; i < 4; ++i) {
            acc2[i][0] = 0ULL; acc2[i][1] = 0ULL; acc2[i][2] = 0ULL; acc2[i][3] = 0ULL;
        }

        #pragma unroll 1
        for (int c2 = 0; c2 < 4; ++c2) {
            const int n0 = c2 * 64;

            // ---- matmul1 (k-pair packed): pre[:, n0:n0+64] ----
            u64 acc1[4][4];   // lanes: (even-k sum + const_bias, odd-k sum)
            {
                const float4 cb = *reinterpret_cast<const float4*>(g_const_bias + n0 + tx*4);
                #pragma unroll
                for (int i = 0; i < 4; ++i) {
                    acc1[i][0] = pack2(cb.x, 0.0f); acc1[i][1] = pack2(cb.y, 0.0f);
                    acc1[i][2] = pack2(cb.z, 0.0f); acc1[i][3] = pack2(cb.w, 0.0f);
                }
            }
            #pragma unroll
            for (int j = 0; j < 3; ++j) {
                const int dj = (j == 0) ? 0 : ((j == 1) ? 31 : 1);  // self, left, right
                int roff[4];
                #pragma unroll
                for (int i = 0; i < 4; ++i) {
                    const int m = ty + 16*i;
                    roff[i] = ((m & 32) | ((m + dj) & 31)) << 7;  // roll within 32-row group
                }
                const u64* Wj = g_W1p + j*16384 + n0 + tx*4;
                #pragma unroll 4
                for (int k0 = 0; k0 < 128; k0 += 4) {
                    const u64* wp = Wj + (k0 >> 1) * 256;
                    const ulonglong2 wA = *reinterpret_cast<const ulonglong2*>(wp);
                    const ulonglong2 wB = *reinterpret_cast<const ulonglong2*>(wp + 2);
                    const ulonglong2 wC = *reinterpret_cast<const ulonglong2*>(wp + 256);
                    const ulonglong2 wD = *reinterpret_cast<const ulonglong2*>(wp + 258);
                    #pragma unroll
                    for (int i = 0; i < 4; ++i) {
                        const ulonglong2 av = *reinterpret_cast<const ulonglong2*>(cells + roff[i] + k0);
                        fma2(acc1[i][0], av.x, wA.x); fma2(acc1[i][1], av.x, wA.y);
                        fma2(acc1[i][2], av.x, wB.x); fma2(acc1[i][3], av.x, wB.y);
                        fma2(acc1[i][0], av.y, wC.x); fma2(acc1[i][1], av.y, wC.y);
                        fma2(acc1[i][2], av.y, wD.x); fma2(acc1[i][3], av.y, wD.y);
                    }
                }
            }

            __syncthreads();   // prior chunk's matmul2 finished reading Hs
            #pragma unroll
            for (int i = 0; i < 4; ++i) {
                const int m = ty + 16*i;
                const float2 f0 = unpack2(acc1[i][0]);
                const float2 f1 = unpack2(acc1[i][1]);
                const float2 f2 = unpack2(acc1[i][2]);
                const float2 f3 = unpack2(acc1[i][3]);
                float4 h;
                h.x = gelu_exact(f0.x + f0.y);
                h.y = gelu_exact(f1.x + f1.y);
                h.z = gelu_exact(f2.x + f2.y);
                h.w = gelu_exact(f3.x + f3.y);
                *reinterpret_cast<float4*>(Hs + m*64 + tx*4) = h;
            }
            __syncthreads();   // Hs chunk ready

            // ---- matmul2 partial: acc2 += Hs(64x64) @ W2[n0:n0+64, :] ----
            const float* W2p = W2 + n0*128 + tx*8;
            #pragma unroll 4
            for (int k = 0; k < 64; k += 2) {
                const ulonglong2 c0 = *reinterpret_cast<const ulonglong2*>(W2p + (k+0)*128);
                const ulonglong2 c1 = *reinterpret_cast<const ulonglong2*>(W2p + (k+0)*128 + 4);
                const ulonglong2 d0 = *reinterpret_cast<const ulonglong2*>(W2p + (k+1)*128);
                const ulonglong2 d1 = *reinterpret_cast<const ulonglong2*>(W2p + (k+1)*128 + 4);
                #pragma unroll
                for (int i = 0; i < 4; ++i) {
                    const int m = ty + 16*i;
                    const float2 hv = *reinterpret_cast<const float2*>(Hs + m*64 + k);
                    const u64 h0 = pack2(hv.x, hv.x), h1 = pack2(hv.y, hv.y);
                    fma2(acc2[i][0], h0, c0.x); fma2(acc2[i][1], h0, c0.y);
                    fma2(acc2[i][2], h0, c1.x); fma2(acc2[i][3], h0, c1.y);
                    fma2(acc2[i][0], h1, d0.x); fma2(acc2[i][1], h1, d0.y);
                    fma2(acc2[i][2], h1, d1.x); fma2(acc2[i][3], h1, d1.y);
                }
            }
        } // n-chunks

        // ---- cells = a*cells + (1-a)*tanh(acc2 + b2) ----
        {
            const float* b2p = b2 + tx*8;
            float bb[8];
            #pragma unroll
            for (int q = 0; q < 8; ++q) bb[q] = b2p[q];
            #pragma unroll
            for (int i = 0; i < 4; ++i) {
                const int m = ty + 16*i;
                float* crow = cells + m*128 + tx*8;
                float4 o0 = *reinterpret_cast<const float4*>(crow);
                float4 o1 = *reinterpret_cast<const float4*>(crow + 4);
                const float2 v0 = unpack2(acc2[i][0]);
                const float2 v1 = unpack2(acc2[i][1]);
                const float2 v2 = unpack2(acc2[i][2]);
                const float2 v3 = unpack2(acc2[i][3]);
                o0.x = a*o0.x + om*tanhf(v0.x + bb[0]);
                o0.y = a*o0.y + om*tanhf(v0.y + bb[1]);
                o0.z = a*o0.z + om*tanhf(v1.x + bb[2]);
                o0.w = a*o0.w + om*tanhf(v1.y + bb[3]);
                o1.x = a*o1.x + om*tanhf(v2.x + bb[4]);
                o1.y = a*o1.y + om*tanhf(v2.y + bb[5]);
                o1.z = a*o1.z + om*tanhf(v3.x + bb[6]);
                o1.w = a*o1.w + om*tanhf(v3.y + bb[7]);
                *reinterpret_cast<float4*>(crow)     = o0;
                *reinterpret_cast<float4*>(crow + 4) = o1;
            }
        }
        __syncthreads();
    } // steps

    // ================= LayerNorm (per row over D=128) =================
    if (tid < 64) {
        float* crow = cells + tid*128;
        float s = 0.f, ss = 0.f;
        #pragma unroll 8
        for (int q = 0; q < 128; q += 4) {
            const float4 v = *reinterpret_cast<const float4*>(crow + q);
            s  += v.x + v.y + v.z + v.w;
            ss += v.x*v.x + v.y*v.y + v.z*v.z + v.w*v.w;
        }
        const float mu  = s * 0.0078125f;
        const float var = ss * 0.0078125f - mu*mu;
        const float inv = rsqrtf(var + 1e-5f);
        #pragma unroll 8
        for (int q = 0; q < 128; q += 4) {
            float4 v = *reinterpret_cast<const float4*>(crow + q);
            const float4 g4 = *reinterpret_cast<const float4*>(ln_g + q);
            const float4 b4 = *reinterpret_cast<const float4*>(ln_b + q);
            v.x = (v.x - mu)*inv*g4.x + b4.x;
            v.y = (v.y - mu)*inv*g4.y + b4.y;
            v.z = (v.z - mu)*inv*g4.z + b4.z;
            v.w = (v.w - mu)*inv*g4.w + b4.w;
            *reinterpret_cast<float4*>(crow + q) = v;
        }
    }
    __syncthreads();

    // ================= head (k-pair packed): out = cells @ head_w =================
    float* outp = out + (size_t)rowbase * 256;
    #pragma unroll 1
    for (int c2 = 0; c2 < 4; ++c2) {
        const int n0 = c2 * 64;
        u64 acc[4][4];
        #pragma unroll
        for (int i = 0; i < 4; ++i) {
            acc[i][0] = 0ULL; acc[i][1] = 0ULL; acc[i][2] = 0ULL; acc[i][3] = 0ULL;
        }
        const u64* Hw = g_Hp + n0 + tx*4;
        #pragma unroll 4
        for (int k0 = 0; k0 < 128; k0 += 4) {
            const u64* wp = Hw + (k0 >> 1) * 256;
            const ulonglong2 wA = *reinterpret_cast<const ulonglong2*>(wp);
            const ulonglong2 wB = *reinterpret_cast<const ulonglong2*>(wp + 2);
            const ulonglong2 wC = *reinterpret_cast<const ulonglong2*>(wp + 256);
            const ulonglong2 wD = *reinterpret_cast<const ulonglong2*>(wp + 258);
            #pragma unroll
            for (int i = 0; i < 4; ++i) {
                const ulonglong2 av = *reinterpret_cast<const ulonglong2*>(cells + ((ty + 16*i) << 7) + k0);
                fma2(acc[i][0], av.x, wA.x); fma2(acc[i][1], av.x, wA.y);
                fma2(acc[i][2], av.x, wB.x); fma2(acc[i][3], av.x, wB.y);
                fma2(acc[i][0], av.y, wC.x); fma2(acc[i][1], av.y, wC.y);
                fma2(acc[i][2], av.y, wD.x); fma2(acc[i][3], av.y, wD.y);
            }
        }
        #pragma unroll
        for (int i = 0; i < 4; ++i) {
            const int m = ty + 16*i;
            const float2 f0 = unpack2(acc[i][0]);
            const float2 f1 = unpack2(acc[i][1]);
            const float2 f2 = unpack2(acc[i][2]);
            const float2 f3 = unpack2(acc[i][3]);
            float4 o;
            o.x = f0.x + f0.y; o.y = f1.x + f1.y;
            o.z = f2.x + f2.y; o.w = f3.x + f3.y;
            *reinterpret_cast<float4*>(outp + m*256 + n0 + tx*4) = o;
        }
    }
}

// ---------------------------------------------------------------------------
extern "C" void kernel_launch(void* const* d_in, const int* in_sizes, int n_in,
                              void* d_out, int out_size)
{
    const int*   tokens    = (const int*)  d_in[0];
    const float* c_states  = (const float*)d_in[1];
    const float* embed     = (const float*)d_in[2];
    const float* pos_embed = (const float*)d_in[3];
    const float* W1        = (const float*)d_in[4];
    const float* b1        = (const float*)d_in[5];
    const float* W2        = (const float*)d_in[6];
    const float* b2        = (const float*)d_in[7];
    const float* Wc1       = (const float*)d_in[8];
    const float* bc1       = (const float*)d_in[9];
    const float* Wc2       = (const float*)d_in[10];
    const float* bc2       = (const float*)d_in[11];
    const float* alpha     = (const float*)d_in[12];
    const float* ln_g      = (const float*)d_in[13];
    const float* ln_b      = (const float*)d_in[14];
    const float* head_w    = (const float*)d_in[15];
    float* out = (float*)d_out;

    cudaFuncSetAttribute(evolve_kernel, cudaFuncAttributeMaxDynamicSharedMemorySize, 49152);

    prep_kernel<<<1, 256>>>(c_states, Wc1, bc1, Wc2, bc2, W1, b1, alpha);
    pack_kernel<<<64, 256>>>(W1, head_w);
    evolve_kernel<<<1024, 256, 49152>>>(tokens, embed, pos_embed, W2, b2,
                                        ln_g, ln_b, out);
}

// round 11
// speedup vs baseline: 4.1724x; 3.8792x over previous
#include <cuda_runtime.h>
#include <cuda_bf16.h>
#include <math.h>

// CellularAutomatonDecoder via mma.sync m16n8k16 bf16 (base-target tensor cores;
// tcgen05 is rejected by the harness's compute_103 PTX stage).
// B=2048, T=32, D=128, V=256, 8 evolve steps.
// CTA = 128 rows (4 seqs x 32 pos). bf16 hi/lo split: 3 MMAs per logical GEMM.
// Roll handled by ldmatrix A-row remapping. Weights streamed via double-buffered
// cp.async from pre-packed [n][k] tile images.

typedef unsigned int u32;

// ------------------------- global scratch -------------------------
__device__ __align__(16) __nv_bfloat16 g_w1t[12 * 16384]; // (j*4 + h*2 + hl)
__device__ __align__(16) __nv_bfloat16 g_w2t[ 4 * 16384]; // (h*2 + hl)
__device__ __align__(16) __nv_bfloat16 g_hdt[ 4 * 16384]; // (h*2 + hl)
__device__ float g_const_bias[256];
__device__ float g_alpha_sig;

// ------------------------- helpers -------------------------
__device__ __forceinline__ u32 smem_u32(const void* p){
    u32 a; asm("{ .reg .u64 t; cvta.to.shared.u64 t, %1; cvt.u32.u64 %0, t; }" : "=r"(a) : "l"(p));
    return a;
}
__device__ __forceinline__ void ldmx4(u32 addr, u32& r0, u32& r1, u32& r2, u32& r3){
    asm volatile("ldmatrix.sync.aligned.m8n8.x4.shared.b16 {%0,%1,%2,%3}, [%4];"
        : "=r"(r0), "=r"(r1), "=r"(r2), "=r"(r3) : "r"(addr));
}
__device__ __forceinline__ void ldmx2(u32 addr, u32& r0, u32& r1){
    asm volatile("ldmatrix.sync.aligned.m8n8.x2.shared.b16 {%0,%1}, [%2];"
        : "=r"(r0), "=r"(r1) : "r"(addr));
}
__device__ __forceinline__ void hmma(float* d, u32 a0, u32 a1, u32 a2, u32 a3, u32 b0, u32 b1){
    asm volatile("mma.sync.aligned.m16n8k16.row.col.f32.bf16.bf16.f32 "
        "{%0,%1,%2,%3},{%4,%5,%6,%7},{%8,%9},{%0,%1,%2,%3};"
        : "+f"(d[0]), "+f"(d[1]), "+f"(d[2]), "+f"(d[3])
        : "r"(a0), "r"(a1), "r"(a2), "r"(a3), "r"(b0), "r"(b1));
}
__device__ __forceinline__ float gelu_exact(float x){
    return 0.5f * x * (1.0f + erff(x * 0.70710678118654752440f));
}
__device__ __forceinline__ __nv_bfloat162 split_hi2(float v0, float v1, __nv_bfloat162& lo){
    __nv_bfloat16 h0 = __float2bfloat16_rn(v0);
    __nv_bfloat16 h1 = __float2bfloat16_rn(v1);
    lo = __halves2bfloat162(__float2bfloat16_rn(v0 - __bfloat162float(h0)),
                            __float2bfloat16_rn(v1 - __bfloat162float(h1)));
    return __halves2bfloat162(h0, h1);
}

// Streamed-tile source schedule. 132 tiles total:
// t = step*16 + h*8 + v; v 0..5 = W1(j=v>>1, hl=v&1); v 6,7 = W2(hl=v-6).
// t >= 128: head (h*2 + hl).
__device__ __forceinline__ const __nv_bfloat16* tile_src(int t){
    if (t >= 132) t = 131;
    if (t < 128){
        const int u = t & 15, h = u >> 3, v = u & 7;
        if (v < 6){ const int j = v >> 1, hl = v & 1; return g_w1t + (j*4 + h*2 + hl)*16384; }
        return g_w2t + (h*2 + (v - 6))*16384;
    }
    return g_hdt + (t - 128)*16384;
}

// One [128m x 128n x 128k] accumulation pass for this warp's 64x32 tile.
// dj = row-roll delta within 32-row groups (0 = identity).
__device__ __forceinline__ void mma_pass(u32 abase, u32 wbase, float (*acc)[4],
                                         int lane, int warpM, int warpN, int dj)
{
    u32 arow[4], brow[4];
    #pragma unroll
    for (int i = 0; i < 4; ++i){
        const int m = warpM*64 + i*16 + (lane & 15);
        const int mr = (m & 96) | ((m + dj) & 31);
        arow[i] = abase + mr*272 + ((lane >> 4) << 4);
    }
    #pragma unroll
    for (int j = 0; j < 4; ++j){
        const int n = warpN*32 + j*8 + (lane & 7);
        brow[j] = wbase + n*272 + (((lane >> 3) & 1) << 4);
    }
    #pragma unroll
    for (int ks = 0; ks < 8; ++ks){
        u32 a[4][4], b[4][2];
        #pragma unroll
        for (int j = 0; j < 4; ++j) ldmx2(brow[j] + ks*32, b[j][0], b[j][1]);
        #pragma unroll
        for (int i = 0; i < 4; ++i) ldmx4(arow[i] + ks*32, a[i][0], a[i][1], a[i][2], a[i][3]);
        #pragma unroll
        for (int i = 0; i < 4; ++i)
            #pragma unroll
            for (int j = 0; j < 4; ++j)
                hmma(acc[i*4+j], a[i][0], a[i][1], a[i][2], a[i][3], b[j][0], b[j][1]);
    }
}

// ------------------------- prep (const_bias, alpha) -------------------------
__global__ void prep_kernel(const float* __restrict__ c_states,
                            const float* __restrict__ Wc1,
                            const float* __restrict__ bc1,
                            const float* __restrict__ Wc2,
                            const float* __restrict__ bc2,
                            const float* __restrict__ W1,
                            const float* __restrict__ b1,
                            const float* __restrict__ alpha)
{
    __shared__ float cp[128];
    __shared__ float h1[256];
    __shared__ float rb[128];
    const int tid = threadIdx.x;
    if (tid < 128)
        cp[tid] = 0.25f * (c_states[tid] + c_states[128+tid] + c_states[256+tid] + c_states[384+tid]);
    __syncthreads();
    {
        float s = bc1[tid];
        #pragma unroll 16
        for (int d = 0; d < 128; ++d) s += cp[d] * Wc1[d*256 + tid];
        h1[tid] = gelu_exact(s);
    }
    __syncthreads();
    if (tid < 128) {
        float s = bc2[tid];
        #pragma unroll 16
        for (int n = 0; n < 256; ++n) s += h1[n] * Wc2[n*128 + tid];
        rb[tid] = s;
    }
    __syncthreads();
    {
        float s = b1[tid];
        #pragma unroll 16
        for (int d = 0; d < 128; ++d) s += rb[d] * W1[(384 + d)*256 + tid];
        g_const_bias[tid] = s;
    }
    if (tid == 0) g_alpha_sig = 1.0f / (1.0f + expf(-alpha[0]));
}

// ------------------------- pack weight tiles ([n][k] bf16 hi/lo) -------------
__global__ void pack_tiles(const float* __restrict__ W1,
                           const float* __restrict__ W2,
                           const float* __restrict__ head_w)
{
    const int idx = blockIdx.x * 256 + threadIdx.x;   // 0..327679
    const int t = idx >> 14;                           // 0..19
    const int e = idx & 16383;
    const int n = e >> 7, k = e & 127;
    float v; __nv_bfloat16* dst;
    if (t < 12) {                       // W1: t = j*4 + h*2 + hl
        const int j = t >> 2, h = (t >> 1) & 1;
        v = W1[(j*128 + k)*256 + h*128 + n];
        dst = g_w1t + t*16384 + e;
    } else if (t < 16) {                // W2: (t-12) = h*2 + hl
        const int u = t - 12, h = u >> 1;
        v = W2[(h*128 + k)*128 + n];
        dst = g_w2t + u*16384 + e;
    } else {                            // head: (t-16) = h*2 + hl
        const int u = t - 16, h = u >> 1;
        v = head_w[k*256 + h*128 + n];
        dst = g_hdt + u*16384 + e;
    }
    const __nv_bfloat16 hi = __float2bfloat16_rn(v);
    *dst = (t & 1) ? __float2bfloat16_rn(v - __bfloat162float(hi)) : hi;
}

// ------------------------- SMEM layout (bytes) -------------------------
// rows stride 272 B (128 bf16 + 16B pad) for all [128x128] bf16 tiles
#define OA_HI   0
#define OA_LO   34816
#define OH_HI   69632
#define OH_LO   104448
#define OW0     139264
#define OW1     174080
#define OCB     208896
#define OB2     209920
#define OLNG    210432
#define OLNB    210944
#define SMEM_TOTAL 211456

// ------------------------- main fused kernel -------------------------
__global__ void __launch_bounds__(256, 1)
evolve_mma(const int*   __restrict__ tokens,
           const float* __restrict__ embed,
           const float* __restrict__ pos_embed,
           const float* __restrict__ b2,
           const float* __restrict__ ln_g,
           const float* __restrict__ ln_b,
           float*       __restrict__ out)
{
    extern __shared__ char smem[];
    const u32 sb  = smem_u32(smem);
    const int tid = threadIdx.x, lane = tid & 31, wid = tid >> 5;
    const int warpM = wid & 1, warpN = wid >> 1;
    const int rowbase = blockIdx.x * 128;

    const u32 SA_HI = sb + OA_HI, SA_LO = sb + OA_LO;
    const u32 SH_HI = sb + OH_HI, SH_LO = sb + OH_LO;
    const u32 wb[2] = { sb + OW0, sb + OW1 };
    float* cb  = (float*)(smem + OCB);
    float* b2s = (float*)(smem + OB2);
    float* lng = (float*)(smem + OLNG);
    float* lnb = (float*)(smem + OLNB);

    cb[tid] = g_const_bias[tid];
    if (tid < 128) { b2s[tid] = b2[tid]; lng[tid] = ln_g[tid]; lnb[tid] = ln_b[tid]; }

    // ---- init cells = embed[token] + pos_embed (bf16 hi/lo split) ----
    {
        const int m = tid >> 1, kh = (tid & 1) * 64;
        const int g = rowbase + m;
        const int tok = __ldg(tokens + g);
        const float* e = embed + tok*128 + kh;
        const float* p = pos_embed + (m & 31)*128 + kh;
        char* hi = smem + OA_HI + m*272 + kh*2;
        char* lo = smem + OA_LO + m*272 + kh*2;
        for (int q = 0; q < 64; q += 2) {
            __nv_bfloat162 l2;
            __nv_bfloat162 h2 = split_hi2(e[q] + p[q], e[q+1] + p[q+1], l2);
            *(__nv_bfloat162*)(hi + q*2) = h2;
            *(__nv_bfloat162*)(lo + q*2) = l2;
        }
    }

#define PREFETCH_TILE(srcp, sbuf) do { \
        const char* _g = (const char*)(srcp); const u32 _sb = (sbuf); \
        _Pragma("unroll") \
        for (int _i = 0; _i < 8; ++_i) { \
            const int _c = tid + _i*256; const int _row = _c >> 4, _seg = _c & 15; \
            asm volatile("cp.async.cg.shared.global [%0], [%1], 16;" :: \
                "r"(_sb + _row*272 + _seg*16), \
                "l"(__cvta_generic_to_global(_g + _c*16)) : "memory"); } \
        asm volatile("cp.async.commit_group;" ::: "memory"); \
    } while(0)
#define NEXT_TILE() do { \
        asm volatile("cp.async.wait_group 0;" ::: "memory"); \
        __syncthreads(); \
        if (tnext < 132) PREFETCH_TILE(tile_src(tnext), wb[pbuf ^ 1]); \
        ++tnext; cur = wb[pbuf]; pbuf ^= 1; \
    } while(0)

    int tnext = 1, pbuf = 0; u32 cur = wb[0];
    PREFETCH_TILE(tile_src(0), wb[0]);
    __syncthreads();   // cells + params visible

    const float aa = g_alpha_sig, om = 1.0f - aa;
    float acc2[16][4];

    // ================= 8 evolution steps =================
    for (int step = 0; step < 8; ++step) {
        #pragma unroll
        for (int x = 0; x < 16; ++x) { acc2[x][0]=0.f; acc2[x][1]=0.f; acc2[x][2]=0.f; acc2[x][3]=0.f; }

        for (int h = 0; h < 2; ++h) {
            float pre[16][4];
            #pragma unroll
            for (int x = 0; x < 16; ++x) { pre[x][0]=0.f; pre[x][1]=0.f; pre[x][2]=0.f; pre[x][3]=0.f; }

            // ---- matmul1: pre = X @ (W1c|W1l|W1r)[:, h-half], roll via A rows ----
            #pragma unroll 1
            for (int j = 0; j < 3; ++j) {
                const int dj = (j == 0) ? 0 : ((j == 1) ? 31 : 1);
                NEXT_TILE();   // W1(j,h) hi
                mma_pass(SA_HI, cur, pre, lane, warpM, warpN, dj);
                mma_pass(SA_LO, cur, pre, lane, warpM, warpN, dj);
                NEXT_TILE();   // W1(j,h) lo
                mma_pass(SA_HI, cur, pre, lane, warpM, warpN, dj);
            }
            // ---- epilogue1: H = gelu(pre + cb), split to bf16 hi/lo ----
            #pragma unroll
            for (int i = 0; i < 4; ++i) {
                #pragma unroll
                for (int j4 = 0; j4 < 4; ++j4) {
                    const int c = warpN*32 + j4*8 + (lane & 3)*2;
                    const float cb0 = cb[h*128 + c], cb1 = cb[h*128 + c + 1];
                    float* d = pre[i*4 + j4];
                    #pragma unroll
                    for (int rr = 0; rr < 2; ++rr) {
                        const int r = warpM*64 + i*16 + (lane >> 2) + rr*8;
                        __nv_bfloat162 l2;
                        __nv_bfloat162 h2 = split_hi2(gelu_exact(d[rr*2]   + cb0),
                                                      gelu_exact(d[rr*2+1] + cb1), l2);
                        *(__nv_bfloat162*)(smem + OH_HI + r*272 + c*2) = h2;
                        *(__nv_bfloat162*)(smem + OH_LO + r*272 + c*2) = l2;
                    }
                }
            }
            // ---- matmul2 partial: acc2 += H @ W2[h-chunk] ----
            NEXT_TILE();   // W2(h) hi   (sync publishes H)
            mma_pass(SH_HI, cur, acc2, lane, warpM, warpN, 0);
            mma_pass(SH_LO, cur, acc2, lane, warpM, warpN, 0);
            NEXT_TILE();   // W2(h) lo
            mma_pass(SH_HI, cur, acc2, lane, warpM, warpN, 0);
        } // h

        // ---- epilogue2: cells = a*cells + (1-a)*tanh(acc2 + b2) ----
        #pragma unroll
        for (int i = 0; i < 4; ++i) {
            #pragma unroll
            for (int j4 = 0; j4 < 4; ++j4) {
                const int c = warpN*32 + j4*8 + (lane & 3)*2;
                const float bb0 = b2s[c], bb1 = b2s[c + 1];
                float* d = acc2[i*4 + j4];
                #pragma unroll
                for (int rr = 0; rr < 2; ++rr) {
                    const int r = warpM*64 + i*16 + (lane >> 2) + rr*8;
                    const u32 offs = r*272 + c*2;
                    __nv_bfloat162 oh = *(__nv_bfloat162*)(smem + OA_HI + offs);
                    __nv_bfloat162 ol = *(__nv_bfloat162*)(smem + OA_LO + offs);
                    const float o0 = __bfloat162float(oh.x) + __bfloat162float(ol.x);
                    const float o1 = __bfloat162float(oh.y) + __bfloat162float(ol.y);
                    const float v0 = aa*o0 + om*tanhf(d[rr*2]   + bb0);
                    const float v1 = aa*o1 + om*tanhf(d[rr*2+1] + bb1);
                    __nv_bfloat162 l2;
                    __nv_bfloat162 h2 = split_hi2(v0, v1, l2);
                    *(__nv_bfloat162*)(smem + OA_HI + offs) = h2;
                    *(__nv_bfloat162*)(smem + OA_LO + offs) = l2;
                }
            }
        }
    } // steps

    __syncthreads();
    // ================= LayerNorm per row (D=128), in-place =================
    if (tid < 128) {
        char* hi = smem + OA_HI + tid*272;
        char* lo = smem + OA_LO + tid*272;
        float s = 0.f, ss = 0.f;
        #pragma unroll 8
        for (int k = 0; k < 128; k += 2) {
            __nv_bfloat162 vh = *(__nv_bfloat162*)(hi + k*2);
            __nv_bfloat162 vl = *(__nv_bfloat162*)(lo + k*2);
            const float v0 = __bfloat162float(vh.x) + __bfloat162float(vl.x);
            const float v1 = __bfloat162float(vh.y) + __bfloat162float(vl.y);
            s += v0 + v1; ss += v0*v0 + v1*v1;
        }
        const float mu  = s * 0.0078125f;
        const float var = ss * 0.0078125f - mu*mu;
        const float inv = rsqrtf(var + 1e-5f);
        #pragma unroll 8
        for (int k = 0; k < 128; k += 2) {
            __nv_bfloat162 vh = *(__nv_bfloat162*)(hi + k*2);
            __nv_bfloat162 vl = *(__nv_bfloat162*)(lo + k*2);
            const float v0 = ((__bfloat162float(vh.x) + __bfloat162float(vl.x)) - mu)*inv*lng[k]   + lnb[k];
            const float v1 = ((__bfloat162float(vh.y) + __bfloat162float(vl.y)) - mu)*inv*lng[k+1] + lnb[k+1];
            __nv_bfloat162 l2;
            __nv_bfloat162 h2 = split_hi2(v0, v1, l2);
            *(__nv_bfloat162*)(hi + k*2) = h2;
            *(__nv_bfloat162*)(lo + k*2) = l2;
        }
    }

    // ================= head: out = cells @ head_w =================
    for (int h = 0; h < 2; ++h) {
        float hacc[16][4];
        #pragma unroll
        for (int x = 0; x < 16; ++x) { hacc[x][0]=0.f; hacc[x][1]=0.f; hacc[x][2]=0.f; hacc[x][3]=0.f; }
        NEXT_TILE();   // head(h) hi   (first call also publishes LN writes)
        mma_pass(SA_HI, cur, hacc, lane, warpM, warpN, 0);
        mma_pass(SA_LO, cur, hacc, lane, warpM, warpN, 0);
        NEXT_TILE();   // head(h) lo
        mma_pass(SA_HI, cur, hacc, lane, warpM, warpN, 0);
        #pragma unroll
        for (int i = 0; i < 4; ++i) {
            #pragma unroll
            for (int j4 = 0; j4 < 4; ++j4) {
                const int c = warpN*32 + j4*8 + (lane & 3)*2;
                float* d = hacc[i*4 + j4];
                #pragma unroll
                for (int rr = 0; rr < 2; ++rr) {
                    const int r = warpM*64 + i*16 + (lane >> 2) + rr*8;
                    *(float2*)(out + (size_t)(rowbase + r)*256 + h*128 + c) =
                        make_float2(d[rr*2], d[rr*2+1]);
                }
            }
        }
    }
#undef PREFETCH_TILE
#undef NEXT_TILE
}

// ---------------------------------------------------------------------------
extern "C" void kernel_launch(void* const* d_in, const int* in_sizes, int n_in,
                              void* d_out, int out_size)
{
    const int*   tokens    = (const int*)  d_in[0];
    const float* c_states  = (const float*)d_in[1];
    const float* embed     = (const float*)d_in[2];
    const float* pos_embed = (const float*)d_in[3];
    const float* W1        = (const float*)d_in[4];
    const float* b1        = (const float*)d_in[5];
    const float* W2        = (const float*)d_in[6];
    const float* b2        = (const float*)d_in[7];
    const float* Wc1       = (const float*)d_in[8];
    const float* bc1       = (const float*)d_in[9];
    const float* Wc2       = (const float*)d_in[10];
    const float* bc2       = (const float*)d_in[11];
    const float* alpha     = (const float*)d_in[12];
    const float* ln_g      = (const float*)d_in[13];
    const float* ln_b      = (const float*)d_in[14];
    const float* head_w    = (const float*)d_in[15];
    float* out = (float*)d_out;

    cudaFuncSetAttribute(evolve_mma, cudaFuncAttributeMaxDynamicSharedMemorySize, SMEM_TOTAL);

    prep_kernel<<<1, 256>>>(c_states, Wc1, bc1, Wc2, bc2, W1, b1, alpha);
    pack_tiles<<<1280, 256>>>(W1, W2, head_w);
    evolve_mma<<<512, 256, SMEM_TOTAL>>>(tokens, embed, pos_embed, b2, ln_g, ln_b, out);
}

// round 12
// speedup vs baseline: 4.3684x; 1.0470x over previous
#include <cuda_runtime.h>
#include <cuda_bf16.h>
#include <math.h>

// CellularAutomatonDecoder via mma.sync m16n8k16 bf16 (base-target tensor cores).
// B=2048, T=32, D=128, V=256, 8 evolve steps.
// CTA = 128 rows (4 seqs x 32 pos). bf16 hi/lo split: 3 MMAs per logical GEMM,
// with the two passes sharing a weight tile fused (B frags loaded once).
// Roll handled by ldmatrix A-row remapping. Weights double-buffered via cp.async.

typedef unsigned int u32;

// ------------------------- global scratch -------------------------
__device__ __align__(16) __nv_bfloat16 g_w1t[12 * 16384]; // (j*4 + h*2 + hl)
__device__ __align__(16) __nv_bfloat16 g_w2t[ 4 * 16384]; // (h*2 + hl)
__device__ __align__(16) __nv_bfloat16 g_hdt[ 4 * 16384]; // (h*2 + hl)
__device__ float g_const_bias[256];
__device__ float g_alpha_sig;

// ------------------------- helpers -------------------------
__device__ __forceinline__ u32 smem_u32(const void* p){
    u32 a; asm("{ .reg .u64 t; cvta.to.shared.u64 t, %1; cvt.u32.u64 %0, t; }" : "=r"(a) : "l"(p));
    return a;
}
__device__ __forceinline__ void ldmx4(u32 addr, u32& r0, u32& r1, u32& r2, u32& r3){
    asm volatile("ldmatrix.sync.aligned.m8n8.x4.shared.b16 {%0,%1,%2,%3}, [%4];"
        : "=r"(r0), "=r"(r1), "=r"(r2), "=r"(r3) : "r"(addr));
}
__device__ __forceinline__ void hmma(float* d, u32 a0, u32 a1, u32 a2, u32 a3, u32 b0, u32 b1){
    asm volatile("mma.sync.aligned.m16n8k16.row.col.f32.bf16.bf16.f32 "
        "{%0,%1,%2,%3},{%4,%5,%6,%7},{%8,%9},{%0,%1,%2,%3};"
        : "+f"(d[0]), "+f"(d[1]), "+f"(d[2]), "+f"(d[3])
        : "r"(a0), "r"(a1), "r"(a2), "r"(a3), "r"(b0), "r"(b1));
}
// exact-enough gelu/tanh (abs err <= ~2e-7; tolerance margin is ~1e-4)
__device__ __forceinline__ float erf_appx(float x){
    const float ax = fabsf(x);
    const float t  = __fdividef(1.0f, fmaf(0.3275911f, ax, 1.0f));
    float p = fmaf(1.061405429f, t, -1.453152027f);
    p = fmaf(p, t, 1.421413741f);
    p = fmaf(p, t, -0.284496736f);
    p = fmaf(p, t, 0.254829592f);
    const float r = 1.0f - (p * t) * __expf(-ax * ax);
    return copysignf(r, x);
}
__device__ __forceinline__ float gelu_fast(float x){
    return 0.5f * x * (1.0f + erf_appx(x * 0.70710678118654752440f));
}
__device__ __forceinline__ float tanh_fast(float x){
    const float e = __expf(-2.0f * fabsf(x));
    const float r = __fdividef(1.0f - e, 1.0f + e);
    return copysignf(r, x);
}
__device__ __forceinline__ float gelu_exact(float x){
    return 0.5f * x * (1.0f + erff(x * 0.70710678118654752440f));
}
__device__ __forceinline__ __nv_bfloat162 split_hi2(float v0, float v1, __nv_bfloat162& lo){
    __nv_bfloat16 h0 = __float2bfloat16_rn(v0);
    __nv_bfloat16 h1 = __float2bfloat16_rn(v1);
    lo = __halves2bfloat162(__float2bfloat16_rn(v0 - __bfloat162float(h0)),
                            __float2bfloat16_rn(v1 - __bfloat162float(h1)));
    return __halves2bfloat162(h0, h1);
}

// Streamed-tile source schedule. 132 tiles total:
// t = step*16 + h*8 + v; v 0..5 = W1(j=v>>1, hl=v&1); v 6,7 = W2(hl=v-6).
// t >= 128: head (h*2 + hl).
__device__ __forceinline__ const __nv_bfloat16* tile_src(int t){
    if (t >= 132) t = 131;
    if (t < 128){
        const int u = t & 15, h = u >> 3, v = u & 7;
        if (v < 6){ const int j = v >> 1, hl = v & 1; return g_w1t + (j*4 + h*2 + hl)*16384; }
        return g_w2t + (h*2 + (v - 6))*16384;
    }
    return g_hdt + (t - 128)*16384;
}

// Fused dual-A pass: acc += A_hi@W + A_lo@W over the warp's 64x32 tile.
// B fragments loaded once per k-step (2x ldmx4). dj = roll within 32-row groups.
__device__ __forceinline__ void mma_pass2(u32 ahi, u32 dlo, u32 wbase, float (*acc)[4],
                                          int lane, int warpM, int warpN, int dj)
{
    u32 arow[4], brow4[2];
    #pragma unroll
    for (int i = 0; i < 4; ++i){
        const int m = warpM*64 + i*16 + (lane & 15);
        const int mr = (m & 96) | ((m + dj) & 31);
        arow[i] = ahi + mr*272 + ((lane >> 4) << 4);
    }
    #pragma unroll
    for (int jp = 0; jp < 2; ++jp){
        const int n = warpN*32 + jp*16 + (((lane >> 4) & 1) << 3) + (lane & 7);
        brow4[jp] = wbase + n*272 + (((lane >> 3) & 1) << 4);
    }
    #pragma unroll
    for (int ks = 0; ks < 8; ++ks){
        u32 b[4][2];
        ldmx4(brow4[0] + ks*32, b[0][0], b[0][1], b[1][0], b[1][1]);
        ldmx4(brow4[1] + ks*32, b[2][0], b[2][1], b[3][0], b[3][1]);
        u32 a[4][4];
        #pragma unroll
        for (int i = 0; i < 4; ++i) ldmx4(arow[i] + ks*32, a[i][0], a[i][1], a[i][2], a[i][3]);
        #pragma unroll
        for (int i = 0; i < 4; ++i)
            #pragma unroll
            for (int j = 0; j < 4; ++j)
                hmma(acc[i*4+j], a[i][0], a[i][1], a[i][2], a[i][3], b[j][0], b[j][1]);
        #pragma unroll
        for (int i = 0; i < 4; ++i) ldmx4(arow[i] + dlo + ks*32, a[i][0], a[i][1], a[i][2], a[i][3]);
        #pragma unroll
        for (int i = 0; i < 4; ++i)
            #pragma unroll
            for (int j = 0; j < 4; ++j)
                hmma(acc[i*4+j], a[i][0], a[i][1], a[i][2], a[i][3], b[j][0], b[j][1]);
    }
}

// Single-A pass: acc += A@W.
__device__ __forceinline__ void mma_pass1(u32 abase, u32 wbase, float (*acc)[4],
                                          int lane, int warpM, int warpN, int dj)
{
    u32 arow[4], brow4[2];
    #pragma unroll
    for (int i = 0; i < 4; ++i){
        const int m = warpM*64 + i*16 + (lane & 15);
        const int mr = (m & 96) | ((m + dj) & 31);
        arow[i] = abase + mr*272 + ((lane >> 4) << 4);
    }
    #pragma unroll
    for (int jp = 0; jp < 2; ++jp){
        const int n = warpN*32 + jp*16 + (((lane >> 4) & 1) << 3) + (lane & 7);
        brow4[jp] = wbase + n*272 + (((lane >> 3) & 1) << 4);
    }
    #pragma unroll
    for (int ks = 0; ks < 8; ++ks){
        u32 b[4][2];
        ldmx4(brow4[0] + ks*32, b[0][0], b[0][1], b[1][0], b[1][1]);
        ldmx4(brow4[1] + ks*32, b[2][0], b[2][1], b[3][0], b[3][1]);
        u32 a[4][4];
        #pragma unroll
        for (int i = 0; i < 4; ++i) ldmx4(arow[i] + ks*32, a[i][0], a[i][1], a[i][2], a[i][3]);
        #pragma unroll
        for (int i = 0; i < 4; ++i)
            #pragma unroll
            for (int j = 0; j < 4; ++j)
                hmma(acc[i*4+j], a[i][0], a[i][1], a[i][2], a[i][3], b[j][0], b[j][1]);
    }
}

// ------------------------- prep (const_bias, alpha) -------------------------
__global__ void __launch_bounds__(1024)
prep_kernel(const float* __restrict__ c_states,
            const float* __restrict__ Wc1,
            const float* __restrict__ bc1,
            const float* __restrict__ Wc2,
            const float* __restrict__ bc2,
            const float* __restrict__ W1,
            const float* __restrict__ b1,
            const float* __restrict__ alpha)
{
    __shared__ float cp[128];
    __shared__ float h1[256];
    __shared__ float rb[128];
    const int tid = threadIdx.x;
    if (tid < 128)
        cp[tid] = 0.25f * (c_states[tid] + c_states[128+tid] + c_states[256+tid] + c_states[384+tid]);
    __syncthreads();
    {   // 256 outputs x 4-way split-K
        const int n = tid >> 2, r = tid & 3;
        float s = 0.f;
        for (int d = r; d < 128; d += 4) s += cp[d] * __ldg(Wc1 + d*256 + n);
        s += __shfl_xor_sync(0xffffffffu, s, 1);
        s += __shfl_xor_sync(0xffffffffu, s, 2);
        if (r == 0) h1[n] = gelu_exact(s + bc1[n]);
    }
    __syncthreads();
    {   // 128 outputs x 8-way split-K
        const int n = tid >> 3, r = tid & 7;
        float s = 0.f;
        for (int k = r; k < 256; k += 8) s += h1[k] * __ldg(Wc2 + k*128 + n);
        s += __shfl_xor_sync(0xffffffffu, s, 1);
        s += __shfl_xor_sync(0xffffffffu, s, 2);
        s += __shfl_xor_sync(0xffffffffu, s, 4);
        if (r == 0) rb[n] = s + bc2[n];
    }
    __syncthreads();
    {   // 256 outputs x 4-way split-K
        const int n = tid >> 2, r = tid & 3;
        float s = 0.f;
        for (int d = r; d < 128; d += 4) s += rb[d] * __ldg(W1 + (384 + d)*256 + n);
        s += __shfl_xor_sync(0xffffffffu, s, 1);
        s += __shfl_xor_sync(0xffffffffu, s, 2);
        if (r == 0) g_const_bias[n] = s + b1[n];
    }
    if (tid == 0) g_alpha_sig = 1.0f / (1.0f + expf(-alpha[0]));
}

// ------------------------- pack weight tiles ([n][k] bf16 hi/lo) -------------
__global__ void pack_tiles(const float* __restrict__ W1,
                           const float* __restrict__ W2,
                           const float* __restrict__ head_w)
{
    const int idx = blockIdx.x * 256 + threadIdx.x;   // 0..327679
    const int t = idx >> 14;                           // 0..19
    const int e = idx & 16383;
    const int n = e >> 7, k = e & 127;
    float v; __nv_bfloat16* dst;
    if (t < 12) {                       // W1: t = j*4 + h*2 + hl
        const int j = t >> 2, h = (t >> 1) & 1;
        v = W1[(j*128 + k)*256 + h*128 + n];
        dst = g_w1t + t*16384 + e;
    } else if (t < 16) {                // W2: (t-12) = h*2 + hl
        const int u = t - 12, h = u >> 1;
        v = W2[(h*128 + k)*128 + n];
        dst = g_w2t + u*16384 + e;
    } else {                            // head: (t-16) = h*2 + hl
        const int u = t - 16, h = u >> 1;
        v = head_w[k*256 + h*128 + n];
        dst = g_hdt + u*16384 + e;
    }
    const __nv_bfloat16 hi = __float2bfloat16_rn(v);
    *dst = (t & 1) ? __float2bfloat16_rn(v - __bfloat162float(hi)) : hi;
}

// ------------------------- SMEM layout (bytes) -------------------------
// rows stride 272 B (128 bf16 + 16B pad) for all [128x128] bf16 tiles
#define OA_HI   0
#define OA_LO   34816
#define OH_HI   69632
#define OH_LO   104448
#define OW0     139264
#define OW1     174080
#define OCB     208896
#define OB2     209920
#define OLNG    210432
#define OLNB    210944
#define SMEM_TOTAL 211456
#define DLO_A   34816   /* OA_LO - OA_HI, == OH_LO - OH_HI */

// ------------------------- main fused kernel -------------------------
__global__ void __launch_bounds__(256, 1)
evolve_mma(const int*   __restrict__ tokens,
           const float* __restrict__ embed,
           const float* __restrict__ pos_embed,
           const float* __restrict__ b2,
           const float* __restrict__ ln_g,
           const float* __restrict__ ln_b,
           float*       __restrict__ out)
{
    extern __shared__ char smem[];
    const u32 sb  = smem_u32(smem);
    const int tid = threadIdx.x, lane = tid & 31, wid = tid >> 5;
    const int warpM = wid & 1, warpN = wid >> 1;
    const int rowbase = blockIdx.x * 128;

    const u32 SA_HI = sb + OA_HI;
    const u32 SH_HI = sb + OH_HI;
    const u32 wb[2] = { sb + OW0, sb + OW1 };
    float* cb  = (float*)(smem + OCB);
    float* b2s = (float*)(smem + OB2);
    float* lng = (float*)(smem + OLNG);
    float* lnb = (float*)(smem + OLNB);

    cb[tid] = g_const_bias[tid];
    if (tid < 128) { b2s[tid] = b2[tid]; lng[tid] = ln_g[tid]; lnb[tid] = ln_b[tid]; }

    // ---- init cells = embed[token] + pos_embed (bf16 hi/lo split) ----
    {
        const int m = tid >> 1, kh = (tid & 1) * 64;
        const int g = rowbase + m;
        const int tok = __ldg(tokens + g);
        const float* e = embed + tok*128 + kh;
        const float* p = pos_embed + (m & 31)*128 + kh;
        char* hi = smem + OA_HI + m*272 + kh*2;
        char* lo = smem + OA_LO + m*272 + kh*2;
        for (int q = 0; q < 64; q += 2) {
            __nv_bfloat162 l2;
            __nv_bfloat162 h2 = split_hi2(e[q] + p[q], e[q+1] + p[q+1], l2);
            *(__nv_bfloat162*)(hi + q*2) = h2;
            *(__nv_bfloat162*)(lo + q*2) = l2;
        }
    }

#define PREFETCH_TILE(srcp, sbuf) do { \
        const char* _g = (const char*)(srcp); const u32 _sb = (sbuf); \
        _Pragma("unroll") \
        for (int _i = 0; _i < 8; ++_i) { \
            const int _c = tid + _i*256; const int _row = _c >> 4, _seg = _c & 15; \
            asm volatile("cp.async.cg.shared.global [%0], [%1], 16;" :: \
                "r"(_sb + _row*272 + _seg*16), \
                "l"(__cvta_generic_to_global(_g + _c*16)) : "memory"); } \
        asm volatile("cp.async.commit_group;" ::: "memory"); \
    } while(0)
#define NEXT_TILE() do { \
        asm volatile("cp.async.wait_group 0;" ::: "memory"); \
        __syncthreads(); \
        if (tnext < 132) PREFETCH_TILE(tile_src(tnext), wb[pbuf ^ 1]); \
        ++tnext; cur = wb[pbuf]; pbuf ^= 1; \
    } while(0)

    int tnext = 1, pbuf = 0; u32 cur = wb[0];
    PREFETCH_TILE(tile_src(0), wb[0]);
    __syncthreads();   // cells + params visible

    const float aa = g_alpha_sig, om = 1.0f - aa;
    float acc2[16][4];

    // ================= 8 evolution steps =================
    for (int step = 0; step < 8; ++step) {
        #pragma unroll
        for (int x = 0; x < 16; ++x) { acc2[x][0]=0.f; acc2[x][1]=0.f; acc2[x][2]=0.f; acc2[x][3]=0.f; }

        for (int h = 0; h < 2; ++h) {
            float pre[16][4];
            #pragma unroll
            for (int x = 0; x < 16; ++x) { pre[x][0]=0.f; pre[x][1]=0.f; pre[x][2]=0.f; pre[x][3]=0.f; }

            // ---- matmul1: pre = X @ (W1c|W1l|W1r)[:, h-half], roll via A rows ----
            #pragma unroll 1
            for (int j = 0; j < 3; ++j) {
                const int dj = (j == 0) ? 0 : ((j == 1) ? 31 : 1);
                NEXT_TILE();   // W1(j,h) hi
                mma_pass2(SA_HI, DLO_A, cur, pre, lane, warpM, warpN, dj);
                NEXT_TILE();   // W1(j,h) lo
                mma_pass1(SA_HI, cur, pre, lane, warpM, warpN, dj);
            }
            // ---- epilogue1: H = gelu(pre + cb), split to bf16 hi/lo ----
            #pragma unroll
            for (int i = 0; i < 4; ++i) {
                #pragma unroll
                for (int j4 = 0; j4 < 4; ++j4) {
                    const int c = warpN*32 + j4*8 + (lane & 3)*2;
                    const float cb0 = cb[h*128 + c], cb1 = cb[h*128 + c + 1];
                    float* d = pre[i*4 + j4];
                    #pragma unroll
                    for (int rr = 0; rr < 2; ++rr) {
                        const int r = warpM*64 + i*16 + (lane >> 2) + rr*8;
                        __nv_bfloat162 l2;
                        __nv_bfloat162 h2 = split_hi2(gelu_fast(d[rr*2]   + cb0),
                                                      gelu_fast(d[rr*2+1] + cb1), l2);
                        *(__nv_bfloat162*)(smem + OH_HI + r*272 + c*2) = h2;
                        *(__nv_bfloat162*)(smem + OH_LO + r*272 + c*2) = l2;
                    }
                }
            }
            // ---- matmul2 partial: acc2 += H @ W2[h-chunk] ----
            NEXT_TILE();   // W2(h) hi   (sync publishes H)
            mma_pass2(SH_HI, DLO_A, cur, acc2, lane, warpM, warpN, 0);
            NEXT_TILE();   // W2(h) lo
            mma_pass1(SH_HI, cur, acc2, lane, warpM, warpN, 0);
        } // h

        // ---- epilogue2: cells = a*cells + (1-a)*tanh(acc2 + b2) ----
        #pragma unroll
        for (int i = 0; i < 4; ++i) {
            #pragma unroll
            for (int j4 = 0; j4 < 4; ++j4) {
                const int c = warpN*32 + j4*8 + (lane & 3)*2;
                const float bb0 = b2s[c], bb1 = b2s[c + 1];
                float* d = acc2[i*4 + j4];
                #pragma unroll
                for (int rr = 0; rr < 2; ++rr) {
                    const int r = warpM*64 + i*16 + (lane >> 2) + rr*8;
                    const u32 offs = r*272 + c*2;
                    __nv_bfloat162 oh = *(__nv_bfloat162*)(smem + OA_HI + offs);
                    __nv_bfloat162 ol = *(__nv_bfloat162*)(smem + OA_LO + offs);
                    const float o0 = __bfloat162float(oh.x) + __bfloat162float(ol.x);
                    const float o1 = __bfloat162float(oh.y) + __bfloat162float(ol.y);
                    const float v0 = aa*o0 + om*tanh_fast(d[rr*2]   + bb0);
                    const float v1 = aa*o1 + om*tanh_fast(d[rr*2+1] + bb1);
                    __nv_bfloat162 l2;
                    __nv_bfloat162 h2 = split_hi2(v0, v1, l2);
                    *(__nv_bfloat162*)(smem + OA_HI + offs) = h2;
                    *(__nv_bfloat162*)(smem + OA_LO + offs) = l2;
                }
            }
        }
    } // steps

    __syncthreads();
    // ================= LayerNorm per row (D=128), in-place =================
    if (tid < 128) {
        char* hi = smem + OA_HI + tid*272;
        char* lo = smem + OA_LO + tid*272;
        float s = 0.f, ss = 0.f;
        #pragma unroll 8
        for (int k = 0; k < 128; k += 2) {
            __nv_bfloat162 vh = *(__nv_bfloat162*)(hi + k*2);
            __nv_bfloat162 vl = *(__nv_bfloat162*)(lo + k*2);
            const float v0 = __bfloat162float(vh.x) + __bfloat162float(vl.x);
            const float v1 = __bfloat162float(vh.y) + __bfloat162float(vl.y);
            s += v0 + v1; ss += v0*v0 + v1*v1;
        }
        const float mu  = s * 0.0078125f;
        const float var = ss * 0.0078125f - mu*mu;
        const float inv = rsqrtf(var + 1e-5f);
        #pragma unroll 8
        for (int k = 0; k < 128; k += 2) {
            __nv_bfloat162 vh = *(__nv_bfloat162*)(hi + k*2);
            __nv_bfloat162 vl = *(__nv_bfloat162*)(lo + k*2);
            const float v0 = ((__bfloat162float(vh.x) + __bfloat162float(vl.x)) - mu)*inv*lng[k]   + lnb[k];
            const float v1 = ((__bfloat162float(vh.y) + __bfloat162float(vl.y)) - mu)*inv*lng[k+1] + lnb[k+1];
            __nv_bfloat162 l2;
            __nv_bfloat162 h2 = split_hi2(v0, v1, l2);
            *(__nv_bfloat162*)(hi + k*2) = h2;
            *(__nv_bfloat162*)(lo + k*2) = l2;
        }
    }

    // ================= head: out = cells @ head_w =================
    for (int h = 0; h < 2; ++h) {
        float hacc[16][4];
        #pragma unroll
        for (int x = 0; x < 16; ++x) { hacc[x][0]=0.f; hacc[x][1]=0.f; hacc[x][2]=0.f; hacc[x][3]=0.f; }
        NEXT_TILE();   // head(h) hi   (first call also publishes LN writes)
        mma_pass2(SA_HI, DLO_A, cur, hacc, lane, warpM, warpN, 0);
        NEXT_TILE();   // head(h) lo
        mma_pass1(SA_HI, cur, hacc, lane, warpM, warpN, 0);
        #pragma unroll
        for (int i = 0; i < 4; ++i) {
            #pragma unroll
            for (int j4 = 0; j4 < 4; ++j4) {
                const int c = warpN*32 + j4*8 + (lane & 3)*2;
                float* d = hacc[i*4 + j4];
                #pragma unroll
                for (int rr = 0; rr < 2; ++rr) {
                    const int r = warpM*64 + i*16 + (lane >> 2) + rr*8;
                    *(float2*)(out + (size_t)(rowbase + r)*256 + h*128 + c) =
                        make_float2(d[rr*2], d[rr*2+1]);
                }
            }
        }
    }
#undef PREFETCH_TILE
#undef NEXT_TILE
}

// ---------------------------------------------------------------------------
extern "C" void kernel_launch(void* const* d_in, const int* in_sizes, int n_in,
                              void* d_out, int out_size)
{
    const int*   tokens    = (const int*)  d_in[0];
    const float* c_states  = (const float*)d_in[1];
    const float* embed     = (const float*)d_in[2];
    const float* pos_embed = (const float*)d_in[3];
    const float* W1        = (const float*)d_in[4];
    const float* b1        = (const float*)d_in[5];
    const float* W2        = (const float*)d_in[6];
    const float* b2        = (const float*)d_in[7];
    const float* Wc1       = (const float*)d_in[8];
    const float* bc1       = (const float*)d_in[9];
    const float* Wc2       = (const float*)d_in[10];
    const float* bc2       = (const float*)d_in[11];
    const float* alpha     = (const float*)d_in[12];
    const float* ln_g      = (const float*)d_in[13];
    const float* ln_b      = (const float*)d_in[14];
    const float* head_w    = (const float*)d_in[15];
    float* out = (float*)d_out;

    cudaFuncSetAttribute(evolve_mma, cudaFuncAttributeMaxDynamicSharedMemorySize, SMEM_TOTAL);

    prep_kernel<<<1, 1024>>>(c_states, Wc1, bc1, Wc2, bc2, W1, b1, alpha);
    pack_tiles<<<1280, 256>>>(W1, W2, head_w);
    evolve_mma<<<512, 256, SMEM_TOTAL>>>(tokens, embed, pos_embed, b2, ln_g, ln_b, out);
}